// round 1
// baseline (speedup 1.0000x reference)
#include <cuda_runtime.h>
#include <math.h>

#define Nn    50000
#define Ee    1600000
#define F     128
#define ALPHA 0.2f

// ---------------- scratch (static device globals; no allocation) -------------
__device__ float d_hw[Nn * F];        // 25.6 MB  (L2-resident during aggregation)
__device__ float d_ssrc[Nn];
__device__ float d_sdst[Nn];
__device__ int   d_rowptr[Nn + 1];
__device__ float d_ew[Ee];            // per-edge exp(e - m)

// ---------------- f32x2 helpers ----------------------------------------------
__device__ __forceinline__ unsigned long long pack2(float x, float y) {
    unsigned long long r;
    asm("mov.b64 %0, {%1, %2};" : "=l"(r) : "f"(x), "f"(y));
    return r;
}
__device__ __forceinline__ void unpack2(unsigned long long v, float& x, float& y) {
    asm("mov.b64 {%0, %1}, %2;" : "=f"(x), "=f"(y) : "l"(v));
}
__device__ __forceinline__ void fma2(unsigned long long& d, unsigned long long a,
                                     unsigned long long b) {
    asm("fma.rn.f32x2 %0, %1, %2, %0;" : "+l"(d) : "l"(a), "l"(b));
}

// =============================================================================
// K1: hw = h @ W  (+ fused s_src = hw·a_src, s_dst = hw·a_dst)
// block = 256 threads, tile = 64 rows x 128 cols.
// warp w owns rows [rowBase + 8w, rowBase + 8w + 8); lane tx owns cols 4tx..4tx+3
// h tile staged transposed in smem so row-pairs load as 64-bit (f32x2 operand).
// W read from global (64 KB, L1-resident). Inner product via fma.rn.f32x2.
// =============================================================================
__global__ __launch_bounds__(256) void gemm_kernel(const float* __restrict__ h,
                                                   const float* __restrict__ W,
                                                   const float* __restrict__ a_src,
                                                   const float* __restrict__ a_dst) {
    __shared__ float hsh[F * 66];   // hsh[k*66 + r], r in [0,64); pad 66 keeps 8B align
    const int tid     = threadIdx.x;
    const int rowBase = blockIdx.x * 64;

    // stage 64x128 h tile, transposed
    #pragma unroll
    for (int idx = tid; idx < 64 * F; idx += 256) {
        int r = idx >> 7, k = idx & 127;
        int gr = rowBase + r;
        float v = (gr < Nn) ? h[gr * F + k] : 0.0f;
        hsh[k * 66 + r] = v;
    }
    __syncthreads();

    const int tx = tid & 31, ty = tid >> 5;       // warp ty, lane tx
    const float4* __restrict__ W4 = reinterpret_cast<const float4*>(W);

    unsigned long long acc[4][4];                 // [row-pair][col]
    #pragma unroll
    for (int p = 0; p < 4; ++p)
        #pragma unroll
        for (int c = 0; c < 4; ++c) acc[p][c] = 0ull;

    const unsigned long long* hbase =
        reinterpret_cast<const unsigned long long*>(&hsh[ty * 8]);

    #pragma unroll 4
    for (int k = 0; k < F; ++k) {
        float4 w = __ldg(&W4[k * 32 + tx]);
        const unsigned long long* hp = hbase + k * 33;   // 66 floats = 33 ull
        unsigned long long h01 = hp[0], h23 = hp[1], h45 = hp[2], h67 = hp[3];
        unsigned long long wx = pack2(w.x, w.x);
        unsigned long long wy = pack2(w.y, w.y);
        unsigned long long wz = pack2(w.z, w.z);
        unsigned long long ww = pack2(w.w, w.w);
        fma2(acc[0][0], h01, wx); fma2(acc[1][0], h23, wx);
        fma2(acc[2][0], h45, wx); fma2(acc[3][0], h67, wx);
        fma2(acc[0][1], h01, wy); fma2(acc[1][1], h23, wy);
        fma2(acc[2][1], h45, wy); fma2(acc[3][1], h67, wy);
        fma2(acc[0][2], h01, wz); fma2(acc[1][2], h23, wz);
        fma2(acc[2][2], h45, wz); fma2(acc[3][2], h67, wz);
        fma2(acc[0][3], h01, ww); fma2(acc[1][3], h23, ww);
        fma2(acc[2][3], h45, ww); fma2(acc[3][3], h67, ww);
    }

    // unpack: vals[r][c] for r in 0..7 (local rows of this warp)
    float vals[8][4];
    #pragma unroll
    for (int p = 0; p < 4; ++p)
        #pragma unroll
        for (int c = 0; c < 4; ++c)
            unpack2(acc[p][c], vals[2 * p][c], vals[2 * p + 1][c]);

    const float4 as = __ldg(&reinterpret_cast<const float4*>(a_src)[tx]);
    const float4 ad = __ldg(&reinterpret_cast<const float4*>(a_dst)[tx]);
    float4* __restrict__ hw4 = reinterpret_cast<float4*>(d_hw);

    #pragma unroll
    for (int r = 0; r < 8; ++r) {
        int gr = rowBase + ty * 8 + r;
        float4 o = make_float4(vals[r][0], vals[r][1], vals[r][2], vals[r][3]);
        if (gr < Nn) hw4[gr * 32 + tx] = o;
        // fused dot products (warp owns the full row)
        float ps = o.x * as.x + o.y * as.y + o.z * as.z + o.w * as.w;
        float pd = o.x * ad.x + o.y * ad.y + o.z * ad.z + o.w * ad.w;
        #pragma unroll
        for (int off = 16; off; off >>= 1) {
            ps += __shfl_xor_sync(0xffffffffu, ps, off);
            pd += __shfl_xor_sync(0xffffffffu, pd, off);
        }
        if (tx == 0 && gr < Nn) { d_ssrc[gr] = ps; d_sdst[gr] = pd; }
    }
}

// =============================================================================
// K2: row_ptr[i] = lower_bound(row, i)   (row is sorted)
// =============================================================================
__global__ void rowptr_kernel(const int* __restrict__ row) {
    int i = blockIdx.x * blockDim.x + threadIdx.x;
    if (i > Nn) return;
    int lo = 0, hi = Ee;
    while (lo < hi) {
        int mid = (lo + hi) >> 1;
        if (row[mid] < i) lo = mid + 1; else hi = mid;
    }
    d_rowptr[i] = lo;
}

// =============================================================================
// K3: one warp per node: segment softmax + weighted gather-accumulate + elu
// =============================================================================
__global__ __launch_bounds__(256) void edge_kernel(const int* __restrict__ col,
                                                   float* __restrict__ out) {
    const int gwid = (blockIdx.x * blockDim.x + threadIdx.x) >> 5;
    const int lane = threadIdx.x & 31;
    if (gwid >= Nn) return;
    const int r  = gwid;
    const int eb = d_rowptr[r];
    const int ee = d_rowptr[r + 1];
    const float ssrc = d_ssrc[r];

    // pass A: segment max of leaky_relu(s_src[r] + s_dst[col])
    float m = -INFINITY;
    for (int e = eb + lane; e < ee; e += 32) {
        float s = ssrc + __ldg(&d_sdst[__ldg(&col[e])]);
        float v = (s > 0.0f) ? s : ALPHA * s;
        m = fmaxf(m, v);
    }
    #pragma unroll
    for (int off = 16; off; off >>= 1)
        m = fmaxf(m, __shfl_xor_sync(0xffffffffu, m, off));

    // pass B: exp / sum, stash weights
    float sum = 0.0f;
    for (int e = eb + lane; e < ee; e += 32) {
        float s = ssrc + __ldg(&d_sdst[__ldg(&col[e])]);
        float v = (s > 0.0f) ? s : ALPHA * s;
        float w = __expf(v - m);
        d_ew[e] = w;
        sum += w;
    }
    #pragma unroll
    for (int off = 16; off; off >>= 1)
        sum += __shfl_xor_sync(0xffffffffu, sum, off);
    const float inv = (ee > eb) ? (1.0f / sum) : 0.0f;

    // pass C: acc += w * hw[col]   (lane owns float4 feature chunk)
    const float4* __restrict__ hw4 = reinterpret_cast<const float4*>(d_hw);
    float4 acc = make_float4(0.f, 0.f, 0.f, 0.f);
    for (int ebase = eb; ebase < ee; ebase += 32) {
        int e  = ebase + lane;
        float wl = 0.0f; int cl = 0;
        if (e < ee) { wl = d_ew[e]; cl = col[e]; }
        int cnt = min(32, ee - ebase);
        for (int j = 0; j < cnt; ++j) {
            float w = __shfl_sync(0xffffffffu, wl, j);
            int   c = __shfl_sync(0xffffffffu, cl, j);
            float4 v = __ldg(&hw4[c * 32 + lane]);
            acc.x += w * v.x; acc.y += w * v.y;
            acc.z += w * v.z; acc.w += w * v.w;
        }
    }
    acc.x *= inv; acc.y *= inv; acc.z *= inv; acc.w *= inv;

    // elu
    float4 o;
    o.x = (acc.x > 0.f) ? acc.x : expm1f(acc.x);
    o.y = (acc.y > 0.f) ? acc.y : expm1f(acc.y);
    o.z = (acc.z > 0.f) ? acc.z : expm1f(acc.z);
    o.w = (acc.w > 0.f) ? acc.w : expm1f(acc.w);
    reinterpret_cast<float4*>(out)[r * 32 + lane] = o;
}

// =============================================================================
extern "C" void kernel_launch(void* const* d_in, const int* in_sizes, int n_in,
                              void* d_out, int out_size) {
    const float* h     = (const float*)d_in[0];
    const float* W     = (const float*)d_in[1];
    const float* a_src = (const float*)d_in[2];
    const float* a_dst = (const float*)d_in[3];
    const int*   row   = (const int*)d_in[4];
    const int*   col   = (const int*)d_in[5];
    float*       out   = (float*)d_out;

    gemm_kernel<<<(Nn + 63) / 64, 256>>>(h, W, a_src, a_dst);
    rowptr_kernel<<<(Nn + 1 + 255) / 256, 256>>>(row);
    edge_kernel<<<(Nn * 32 + 255) / 256, 256>>>(col, out);
}

// round 2
// speedup vs baseline: 1.0331x; 1.0331x over previous
#include <cuda_runtime.h>
#include <cuda_fp16.h>
#include <math.h>

#define Nn    50000
#define Ee    1600000
#define F     128
#define ALPHA 0.2f

typedef unsigned long long ull;

// ---------------- scratch (static device globals; no allocation) -------------
__device__ __half d_hwh[Nn * F];      // 12.8 MB fp16 hw (L2-resident)
__device__ float  d_ssrc[Nn];
__device__ float  d_sdst[Nn];
__device__ int    d_rowptr[Nn + 1];
__device__ float  d_sc[Ee];           // per-edge pre-softmax score

// ---------------- f32x2 helpers ----------------------------------------------
__device__ __forceinline__ ull pack2(float x, float y) {
    ull r;
    asm("mov.b64 %0, {%1, %2};" : "=l"(r) : "f"(x), "f"(y));
    return r;
}
__device__ __forceinline__ void unpack2(ull v, float& x, float& y) {
    asm("mov.b64 {%0, %1}, %2;" : "=f"(x), "=f"(y) : "l"(v));
}
__device__ __forceinline__ void fma2(ull& d, ull a, ull b) {
    asm("fma.rn.f32x2 %0, %1, %2, %0;" : "+l"(d) : "l"(a), "l"(b));
}

// =============================================================================
// K1: hw = h @ W  (fp16 store) + fused s_src = hw·a_src, s_dst = hw·a_dst
// 128x128 tile, BK=16, 256 threads, 8x8 register blocking, f32x2 FMA,
// double-buffered smem with register prefetch.
// =============================================================================
__global__ __launch_bounds__(256) void gemm_kernel(const float* __restrict__ h,
                                                   const float* __restrict__ W,
                                                   const float* __restrict__ a_src,
                                                   const float* __restrict__ a_dst) {
    __shared__ float As[2][16][128];   // k-major (transposed h tile)
    __shared__ float Bs[2][16][128];   // W chunk, row-major

    const int t       = threadIdx.x;
    const int rowBase = blockIdx.x * 128;
    const int tx = t & 15, ty = t >> 4;       // 16x16 thread grid, 8x8 each

    // A load mapping: thread owns tile row am, k-offsets akg..akg+7
    const int  am   = t & 127;
    const int  akg  = (t >> 7) * 8;           // 0 or 8
    const int  arow = rowBase + am;
    const bool aok  = arow < Nn;
    const float4* __restrict__ h4 = reinterpret_cast<const float4*>(h);
    // B load mapping: warp (t>>5) owns k rows (t>>5) and (t>>5)+8
    const int bk = t >> 5;
    const int bn = (t & 31) * 4;
    const float4* __restrict__ W4 = reinterpret_cast<const float4*>(W);

    float4 a0, a1, b0, b1;

    // prologue: stage 0
    if (aok) {
        a0 = __ldg(&h4[arow * 32 + (akg >> 2)]);
        a1 = __ldg(&h4[arow * 32 + (akg >> 2) + 1]);
    } else {
        a0 = make_float4(0.f, 0.f, 0.f, 0.f); a1 = a0;
    }
    b0 = __ldg(&W4[bk * 32 + (bn >> 2)]);
    b1 = __ldg(&W4[(bk + 8) * 32 + (bn >> 2)]);

    As[0][akg + 0][am] = a0.x; As[0][akg + 1][am] = a0.y;
    As[0][akg + 2][am] = a0.z; As[0][akg + 3][am] = a0.w;
    As[0][akg + 4][am] = a1.x; As[0][akg + 5][am] = a1.y;
    As[0][akg + 6][am] = a1.z; As[0][akg + 7][am] = a1.w;
    *reinterpret_cast<float4*>(&Bs[0][bk][bn])     = b0;
    *reinterpret_cast<float4*>(&Bs[0][bk + 8][bn]) = b1;
    __syncthreads();

    ull acc[8][4];
    #pragma unroll
    for (int i = 0; i < 8; ++i)
        #pragma unroll
        for (int j = 0; j < 4; ++j) acc[i][j] = 0ull;

    #pragma unroll 1
    for (int s = 0; s < 8; ++s) {
        const int buf = s & 1;
        if (s < 7) {
            const int nk = (s + 1) * 16;
            if (aok) {
                a0 = __ldg(&h4[arow * 32 + ((nk + akg) >> 2)]);
                a1 = __ldg(&h4[arow * 32 + ((nk + akg) >> 2) + 1]);
            }
            b0 = __ldg(&W4[(nk + bk) * 32 + (bn >> 2)]);
            b1 = __ldg(&W4[(nk + bk + 8) * 32 + (bn >> 2)]);
        }

        #pragma unroll
        for (int k = 0; k < 16; ++k) {
            float4 x0 = *reinterpret_cast<const float4*>(&As[buf][k][ty * 8]);
            float4 x1 = *reinterpret_cast<const float4*>(&As[buf][k][ty * 8 + 4]);
            float4 y0 = *reinterpret_cast<const float4*>(&Bs[buf][k][tx * 8]);
            float4 y1 = *reinterpret_cast<const float4*>(&Bs[buf][k][tx * 8 + 4]);
            ull pb0 = pack2(y0.x, y0.y), pb1 = pack2(y0.z, y0.w);
            ull pb2 = pack2(y1.x, y1.y), pb3 = pack2(y1.z, y1.w);
            float av[8] = {x0.x, x0.y, x0.z, x0.w, x1.x, x1.y, x1.z, x1.w};
            #pragma unroll
            for (int i = 0; i < 8; ++i) {
                ull pa = pack2(av[i], av[i]);
                fma2(acc[i][0], pa, pb0);
                fma2(acc[i][1], pa, pb1);
                fma2(acc[i][2], pa, pb2);
                fma2(acc[i][3], pa, pb3);
            }
        }

        if (s < 7) {
            const int nb = buf ^ 1;
            As[nb][akg + 0][am] = a0.x; As[nb][akg + 1][am] = a0.y;
            As[nb][akg + 2][am] = a0.z; As[nb][akg + 3][am] = a0.w;
            As[nb][akg + 4][am] = a1.x; As[nb][akg + 5][am] = a1.y;
            As[nb][akg + 6][am] = a1.z; As[nb][akg + 7][am] = a1.w;
            *reinterpret_cast<float4*>(&Bs[nb][bk][bn])     = b0;
            *reinterpret_cast<float4*>(&Bs[nb][bk + 8][bn]) = b1;
        }
        __syncthreads();
    }

    // epilogue: fp16 store + fused score dots
    float asrc[8], adst[8];
    {
        float4 s0 = __ldg(&reinterpret_cast<const float4*>(a_src)[tx * 2]);
        float4 s1 = __ldg(&reinterpret_cast<const float4*>(a_src)[tx * 2 + 1]);
        asrc[0]=s0.x; asrc[1]=s0.y; asrc[2]=s0.z; asrc[3]=s0.w;
        asrc[4]=s1.x; asrc[5]=s1.y; asrc[6]=s1.z; asrc[7]=s1.w;
        float4 d0 = __ldg(&reinterpret_cast<const float4*>(a_dst)[tx * 2]);
        float4 d1 = __ldg(&reinterpret_cast<const float4*>(a_dst)[tx * 2 + 1]);
        adst[0]=d0.x; adst[1]=d0.y; adst[2]=d0.z; adst[3]=d0.w;
        adst[4]=d1.x; adst[5]=d1.y; adst[6]=d1.z; adst[7]=d1.w;
    }

    #pragma unroll
    for (int i = 0; i < 8; ++i) {
        const int gr = rowBase + ty * 8 + i;
        float c[8];
        unpack2(acc[i][0], c[0], c[1]);
        unpack2(acc[i][1], c[2], c[3]);
        unpack2(acc[i][2], c[4], c[5]);
        unpack2(acc[i][3], c[6], c[7]);

        if (gr < Nn) {
            __half2 h0 = __float22half2_rn(make_float2(c[0], c[1]));
            __half2 h1 = __float22half2_rn(make_float2(c[2], c[3]));
            __half2 h2 = __float22half2_rn(make_float2(c[4], c[5]));
            __half2 h3 = __float22half2_rn(make_float2(c[6], c[7]));
            uint4 u;
            u.x = *reinterpret_cast<unsigned*>(&h0);
            u.y = *reinterpret_cast<unsigned*>(&h1);
            u.z = *reinterpret_cast<unsigned*>(&h2);
            u.w = *reinterpret_cast<unsigned*>(&h3);
            *reinterpret_cast<uint4*>(&d_hwh[gr * 128 + tx * 8]) = u;
        }

        float ps = 0.f, pd = 0.f;
        #pragma unroll
        for (int j = 0; j < 8; ++j) { ps += c[j] * asrc[j]; pd += c[j] * adst[j]; }
        #pragma unroll
        for (int off = 8; off; off >>= 1) {
            ps += __shfl_xor_sync(0xffffffffu, ps, off);
            pd += __shfl_xor_sync(0xffffffffu, pd, off);
        }
        if (tx == 0 && gr < Nn) { d_ssrc[gr] = ps; d_sdst[gr] = pd; }
    }
}

// =============================================================================
// K2: row_ptr[i] = lower_bound(row, i)
// =============================================================================
__global__ void rowptr_kernel(const int* __restrict__ row) {
    int i = blockIdx.x * blockDim.x + threadIdx.x;
    if (i > Nn) return;
    int lo = 0, hi = Ee;
    while (lo < hi) {
        int mid = (lo + hi) >> 1;
        if (row[mid] < i) lo = mid + 1; else hi = mid;
    }
    d_rowptr[i] = lo;
}

// =============================================================================
// K3: warp-per-node: fused online-softmax (max+sum in one pass) + fp16 gather
// =============================================================================
__global__ __launch_bounds__(256) void edge_kernel(const int* __restrict__ col,
                                                   float* __restrict__ out) {
    const int gw   = (blockIdx.x * blockDim.x + threadIdx.x) >> 5;
    const int lane = threadIdx.x & 31;
    if (gw >= Nn) return;
    const int   eb   = d_rowptr[gw];
    const int   ee   = d_rowptr[gw + 1];
    const float ssrc = d_ssrc[gw];

    // fused pass: score + online max/sum
    float m = -1e30f, sum = 0.f;
    for (int e = eb + lane; e < ee; e += 32) {
        float s = ssrc + __ldg(&d_sdst[__ldg(&col[e])]);
        float v = (s > 0.f) ? s : ALPHA * s;
        d_sc[e] = v;
        float mn = fmaxf(m, v);
        sum = sum * __expf(m - mn) + __expf(v - mn);
        m = mn;
    }
    #pragma unroll
    for (int off = 16; off; off >>= 1) {
        float mo = __shfl_xor_sync(0xffffffffu, m, off);
        float so = __shfl_xor_sync(0xffffffffu, sum, off);
        float mn = fmaxf(m, mo);
        sum = sum * __expf(m - mn) + so * __expf(mo - mn);
        m = mn;
    }
    const float inv = (ee > eb) ? (1.f / sum) : 0.f;

    // gather-accumulate pass (fp16 rows, 256B/edge)
    const uint2* __restrict__ hw2 = reinterpret_cast<const uint2*>(d_hwh);
    float4 acc = make_float4(0.f, 0.f, 0.f, 0.f);
    for (int e0 = eb; e0 < ee; e0 += 32) {
        int e = e0 + lane;
        float wl = 0.f; int cl = 0;
        if (e < ee) {
            wl = __expf(d_sc[e] - m) * inv;
            cl = __ldg(&col[e]);
        }
        const int cnt = min(32, ee - e0);
        for (int j = 0; j < cnt; ++j) {
            float w = __shfl_sync(0xffffffffu, wl, j);
            int   c = __shfl_sync(0xffffffffu, cl, j);
            uint2 q = __ldg(&hw2[c * 32 + lane]);
            float2 f0 = __half22float2(*reinterpret_cast<__half2*>(&q.x));
            float2 f1 = __half22float2(*reinterpret_cast<__half2*>(&q.y));
            acc.x += w * f0.x; acc.y += w * f0.y;
            acc.z += w * f1.x; acc.w += w * f1.y;
        }
    }

    float4 o;
    o.x = (acc.x > 0.f) ? acc.x : expm1f(acc.x);
    o.y = (acc.y > 0.f) ? acc.y : expm1f(acc.y);
    o.z = (acc.z > 0.f) ? acc.z : expm1f(acc.z);
    o.w = (acc.w > 0.f) ? acc.w : expm1f(acc.w);
    reinterpret_cast<float4*>(out)[gw * 32 + lane] = o;
}

// =============================================================================
extern "C" void kernel_launch(void* const* d_in, const int* in_sizes, int n_in,
                              void* d_out, int out_size) {
    const float* h     = (const float*)d_in[0];
    const float* W     = (const float*)d_in[1];
    const float* a_src = (const float*)d_in[2];
    const float* a_dst = (const float*)d_in[3];
    const int*   row   = (const int*)d_in[4];
    const int*   col   = (const int*)d_in[5];
    float*       out   = (float*)d_out;

    gemm_kernel<<<(Nn + 127) / 128, 256>>>(h, W, a_src, a_dst);
    rowptr_kernel<<<(Nn + 1 + 255) / 256, 256>>>(row);
    edge_kernel<<<(Nn * 32 + 255) / 256, 256>>>(col, out);
}